// round 1
// baseline (speedup 1.0000x reference)
#include <cuda_runtime.h>
#include <math.h>

#define N_TOK 4096
#define HDIM  2048
#define NEXP  24
#define IDIM  512
#define SDIM  2048
#define TOPK  6

#define BM 128
#define BN 128
#define BK 8
#define TILES_PER_E 32                       // 4096/128 worst case rows per expert
#define SLOT_CAP (N_TOK*TOPK + NEXP*BM)      // 24576 + 3072 = 27648

// ---------------- scratch (static device globals; no allocation) ----------------
__device__ int   g_topk_idx[N_TOK*TOPK];
__device__ float g_topk_w[N_TOK*TOPK];
__device__ int   g_counts[NEXP];
__device__ int   g_cursor[NEXP];
__device__ int   g_off[NEXP];
__device__ int   g_padded[NEXP];
__device__ int   g_slot_token[SLOT_CAP];
__device__ int   g_slot_of[N_TOK*TOPK];
__device__ float g_buf1[SLOT_CAP*IDIM];      // 14.2M floats; also holds [N_TOK,SDIM]=8.4M for shared
__device__ float g_buf3[SLOT_CAP*IDIM];
__device__ float g_y[(size_t)SLOT_CAP*HDIM]; // per-slot routed outputs

// ---------------- gating ----------------
__global__ void gate_kernel(const float* __restrict__ x, const float* __restrict__ gw) {
    int warp = (blockIdx.x * blockDim.x + threadIdx.x) >> 5;
    int lane = threadIdx.x & 31;
    if (warp >= N_TOK) return;
    const float* xr = x + (size_t)warp * HDIM;

    float acc[NEXP];
#pragma unroll
    for (int e = 0; e < NEXP; e++) acc[e] = 0.f;
    for (int h = lane; h < HDIM; h += 32) {
        float xv = xr[h];
#pragma unroll
        for (int e = 0; e < NEXP; e++) acc[e] += xv * gw[e*HDIM + h];
    }
#pragma unroll
    for (int e = 0; e < NEXP; e++) {
        float a = acc[e];
#pragma unroll
        for (int o = 16; o; o >>= 1) a += __shfl_xor_sync(0xffffffffu, a, o);
        acc[e] = 1.f / (1.f + expf(-a));   // sigmoid score
    }
    if (lane == 0) {
        bool used[NEXP];
#pragma unroll
        for (int e = 0; e < NEXP; e++) used[e] = false;
        int idxs[TOPK]; float vals[TOPK]; float wsum = 0.f;
        for (int k = 0; k < TOPK; k++) {
            int bi = -1; float bv = -1e30f;
            for (int e = 0; e < NEXP; e++)
                if (!used[e] && acc[e] > bv) { bv = acc[e]; bi = e; }
            used[bi] = true; idxs[k] = bi; vals[k] = bv; wsum += bv;
        }
        float inv = 1.f / (wsum + 1e-9f);
        for (int k = 0; k < TOPK; k++) {
            g_topk_idx[warp*TOPK + k] = idxs[k];
            g_topk_w[warp*TOPK + k]   = vals[k] * inv;
            atomicAdd(&g_counts[idxs[k]], 1);
        }
    }
}

__global__ void zero_counts_kernel() {
    int t = threadIdx.x;
    if (t < NEXP) { g_counts[t] = 0; g_cursor[t] = 0; }
}

__global__ void offsets_kernel() {
    if (threadIdx.x == 0) {
        int off = 0;
        for (int e = 0; e < NEXP; e++) {
            g_off[e] = off;
            int p = (g_counts[e] + BM - 1) / BM * BM;
            g_padded[e] = p;
            off += p;
        }
    }
}

__global__ void fill_slots_kernel() {
    int i = blockIdx.x * blockDim.x + threadIdx.x;
    if (i < SLOT_CAP) g_slot_token[i] = -1;
}

__global__ void scatter_kernel() {
    int i = blockIdx.x * blockDim.x + threadIdx.x;
    if (i >= N_TOK * TOPK) return;
    int e = g_topk_idx[i];
    int pos = g_off[e] + atomicAdd(&g_cursor[e], 1);
    g_slot_token[pos] = i / TOPK;
    g_slot_of[i] = pos;
}

// ---------------- SGEMM core (128x128x8, 256 threads, 8x8 microtile) ----------------
__device__ __forceinline__ void gemm_tile(
    const float* __restrict__ Abase, int a_ldk,   // A row-major, leading dim a_ldk
    const int* tok,                               // smem token list (gather) or nullptr
    const float* __restrict__ B, int Nc, int Kc,  // B row-major [Kc, Nc]
    float* __restrict__ Crow0, int col0, int accumulate)
{
    __shared__ float As[BK][BM];
    __shared__ float Bs[BK][BN];

    int tid = threadIdx.x;
    int arow = tid >> 1;
    int acol = (tid & 1) * 4;
    int brow = tid >> 5;
    int bcol = (tid & 31) * 4;
    int ty = tid >> 4;
    int tx = tid & 15;

    float acc[8][8];
#pragma unroll
    for (int i = 0; i < 8; i++)
#pragma unroll
        for (int j = 0; j < 8; j++) acc[i][j] = 0.f;

    const float* arowptr;
    bool avalid = true;
    if (tok) {
        int t = tok[arow];
        avalid = (t >= 0);
        arowptr = Abase + (size_t)(avalid ? t : 0) * a_ldk;
    } else {
        arowptr = Abase + (size_t)arow * a_ldk;
    }

    float4 av = avalid ? *(const float4*)(arowptr + acol)
                       : make_float4(0.f, 0.f, 0.f, 0.f);
    float4 bv = *(const float4*)(B + (size_t)brow * Nc + col0 + bcol);

    for (int k0 = 0; k0 < Kc; k0 += BK) {
        As[acol + 0][arow] = av.x;
        As[acol + 1][arow] = av.y;
        As[acol + 2][arow] = av.z;
        As[acol + 3][arow] = av.w;
        *(float4*)&Bs[brow][bcol] = bv;
        __syncthreads();

        int kn = k0 + BK;
        if (kn < Kc) {
            av = avalid ? *(const float4*)(arowptr + kn + acol)
                        : make_float4(0.f, 0.f, 0.f, 0.f);
            bv = *(const float4*)(B + (size_t)(kn + brow) * Nc + col0 + bcol);
        }

#pragma unroll
        for (int kk = 0; kk < BK; kk++) {
            float a0[8], b0[8];
            *(float4*)&a0[0] = *(float4*)&As[kk][ty * 8];
            *(float4*)&a0[4] = *(float4*)&As[kk][ty * 8 + 4];
            *(float4*)&b0[0] = *(float4*)&Bs[kk][tx * 8];
            *(float4*)&b0[4] = *(float4*)&Bs[kk][tx * 8 + 4];
#pragma unroll
            for (int i = 0; i < 8; i++)
#pragma unroll
                for (int j = 0; j < 8; j++) acc[i][j] += a0[i] * b0[j];
        }
        __syncthreads();
    }

#pragma unroll
    for (int i = 0; i < 8; i++) {
        float* crow = Crow0 + (size_t)(ty * 8 + i) * Nc + col0 + tx * 8;
        if (accumulate) {
            float4 c0 = *(float4*)crow;
            float4 c1 = *(float4*)(crow + 4);
            c0.x += acc[i][0]; c0.y += acc[i][1]; c0.z += acc[i][2]; c0.w += acc[i][3];
            c1.x += acc[i][4]; c1.y += acc[i][5]; c1.z += acc[i][6]; c1.w += acc[i][7];
            *(float4*)crow = c0; *(float4*)(crow + 4) = c1;
        } else {
            float4 c0 = make_float4(acc[i][0], acc[i][1], acc[i][2], acc[i][3]);
            float4 c1 = make_float4(acc[i][4], acc[i][5], acc[i][6], acc[i][7]);
            *(float4*)crow = c0; *(float4*)(crow + 4) = c1;
        }
    }
}

__global__ void __launch_bounds__(256) sgemm_plain(
    const float* __restrict__ A, const float* __restrict__ B, float* __restrict__ C,
    int Nc, int Kc, int accumulate)
{
    int row0 = blockIdx.y * BM;
    int col0 = blockIdx.x * BN;
    gemm_tile(A + (size_t)row0 * Kc, Kc, nullptr, B, Nc, Kc,
              C + (size_t)row0 * Nc, col0, accumulate);
}

// routed GEMM1: gather token rows of x, per-expert weight slice [HDIM, IDIM]
__global__ void __launch_bounds__(256) sgemm_gather(
    const float* __restrict__ X, const float* __restrict__ Wbase, float* __restrict__ Cbase)
{
    int e  = blockIdx.y >> 5;       // /TILES_PER_E
    int lt = blockIdx.y & 31;
    if (lt * BM >= g_padded[e]) return;
    int slot0 = g_off[e] + lt * BM;

    __shared__ int tok[BM];
    if (threadIdx.x < BM) tok[threadIdx.x] = g_slot_token[slot0 + threadIdx.x];
    __syncthreads();

    gemm_tile(X, HDIM, tok, Wbase + (size_t)e * HDIM * IDIM, IDIM, HDIM,
              Cbase + (size_t)slot0 * IDIM, blockIdx.x * BN, 0);
}

// routed GEMM2: [slots, IDIM] @ w2[e] [IDIM, HDIM] -> Y[slots, HDIM]
__global__ void __launch_bounds__(256) sgemm_routed2(
    const float* __restrict__ G, const float* __restrict__ W2base, float* __restrict__ Y)
{
    int e  = blockIdx.y >> 5;
    int lt = blockIdx.y & 31;
    if (lt * BM >= g_padded[e]) return;
    int slot0 = g_off[e] + lt * BM;
    gemm_tile(G + (size_t)slot0 * IDIM, IDIM, nullptr,
              W2base + (size_t)e * IDIM * HDIM, HDIM, IDIM,
              Y + (size_t)slot0 * HDIM, blockIdx.x * BN, 0);
}

// ---------------- elementwise ----------------
__global__ void silu_mul_kernel(float* __restrict__ a, const float* __restrict__ b, int n) {
    int i = blockIdx.x * blockDim.x + threadIdx.x;
    if (i < n) {
        float v = a[i];
        float s = v / (1.f + expf(-v));   // silu
        a[i] = s * b[i];
    }
}

__global__ void combine_kernel(float* __restrict__ out) {
    int n = blockIdx.x;
    int slot[TOPK]; float w[TOPK];
#pragma unroll
    for (int k = 0; k < TOPK; k++) {
        slot[k] = g_slot_of[n*TOPK + k];
        w[k]    = g_topk_w[n*TOPK + k];
    }
    for (int h = threadIdx.x * 4; h < HDIM; h += blockDim.x * 4) {
        float4 o = *(float4*)(out + (size_t)n * HDIM + h);
#pragma unroll
        for (int k = 0; k < TOPK; k++) {
            const float4 y = *(const float4*)(g_y + (size_t)slot[k] * HDIM + h);
            o.x += w[k] * y.x; o.y += w[k] * y.y;
            o.z += w[k] * y.z; o.w += w[k] * y.w;
        }
        *(float4*)(out + (size_t)n * HDIM + h) = o;
    }
}

__global__ void zero_tail_kernel(float* out, int start, int total) {
    int i = start + blockIdx.x * blockDim.x + threadIdx.x;
    if (i < total) out[i] = 0.f;
}

// ---------------- launch ----------------
extern "C" void kernel_launch(void* const* d_in, const int* in_sizes, int n_in,
                              void* d_out, int out_size) {
    const float* x   = (const float*)d_in[0];
    const float* gw  = (const float*)d_in[1];
    const float* sw1 = (const float*)d_in[2];
    const float* sw2 = (const float*)d_in[3];
    const float* sw3 = (const float*)d_in[4];
    const float* rw1 = (const float*)d_in[5];
    const float* rw2 = (const float*)d_in[6];
    const float* rw3 = (const float*)d_in[7];
    float* out = (float*)d_out;

    float *buf1, *buf3, *ybuf;
    cudaGetSymbolAddress((void**)&buf1, g_buf1);
    cudaGetSymbolAddress((void**)&buf3, g_buf3);
    cudaGetSymbolAddress((void**)&ybuf, g_y);

    // routing
    zero_counts_kernel<<<1, 32>>>();
    gate_kernel<<<N_TOK/8, 256>>>(x, gw);
    offsets_kernel<<<1, 1>>>();
    fill_slots_kernel<<<(SLOT_CAP + 255)/256, 256>>>();
    scatter_kernel<<<(N_TOK*TOPK + 255)/256, 256>>>();

    // shared experts: out = sum_e (silu(x@w1)*(x@w3)) @ w2
    for (int e = 0; e < 2; e++) {
        sgemm_plain<<<dim3(SDIM/BN, N_TOK/BM), 256>>>(x, sw1 + (size_t)e*HDIM*SDIM, buf1, SDIM, HDIM, 0);
        sgemm_plain<<<dim3(SDIM/BN, N_TOK/BM), 256>>>(x, sw3 + (size_t)e*HDIM*SDIM, buf3, SDIM, HDIM, 0);
        silu_mul_kernel<<<(N_TOK*SDIM + 255)/256, 256>>>(buf1, buf3, N_TOK*SDIM);
        sgemm_plain<<<dim3(HDIM/BN, N_TOK/BM), 256>>>(buf1, sw2 + (size_t)e*SDIM*HDIM, out, HDIM, SDIM, e);
    }

    // routed experts (sparse: only gathered slots)
    sgemm_gather<<<dim3(IDIM/BN, NEXP*TILES_PER_E), 256>>>(x, rw1, buf1);
    sgemm_gather<<<dim3(IDIM/BN, NEXP*TILES_PER_E), 256>>>(x, rw3, buf3);
    silu_mul_kernel<<<(SLOT_CAP*IDIM + 255)/256, 256>>>(buf1, buf3, SLOT_CAP*IDIM);
    sgemm_routed2<<<dim3(HDIM/BN, NEXP*TILES_PER_E), 256>>>(buf1, rw2, ybuf);

    // combine routed into out (deterministic: per-token fixed-order sum)
    combine_kernel<<<N_TOK, 256>>>(out);

    int tail = out_size - N_TOK*HDIM;
    if (tail > 0)
        zero_tail_kernel<<<(tail + 255)/256, 256>>>(out, N_TOK*HDIM, out_size);
}

// round 2
// speedup vs baseline: 1.0008x; 1.0008x over previous
#include <cuda_runtime.h>
#include <math.h>

#define N_TOK 4096
#define HDIM  2048
#define NEXP  24
#define IDIM  512
#define SDIM  2048
#define TOPK  6

#define BM 128
#define BN 128
#define BK 8
#define TILES_PER_E 32                       // 4096/128 worst case rows per expert
#define SLOT_CAP (N_TOK*TOPK + NEXP*BM)      // 24576 + 3072 = 27648

// ---------------- scratch (static device globals; no allocation) ----------------
__device__ int   g_topk_idx[N_TOK*TOPK];
__device__ float g_topk_w[N_TOK*TOPK];
__device__ int   g_counts[NEXP];
__device__ int   g_cursor[NEXP];
__device__ int   g_off[NEXP];
__device__ int   g_padded[NEXP];
__device__ int   g_slot_token[SLOT_CAP];
__device__ int   g_slot_of[N_TOK*TOPK];
__device__ float g_buf1[SLOT_CAP*IDIM];      // 14.2M floats; also holds [N_TOK,SDIM]=8.4M for shared
__device__ float g_buf3[SLOT_CAP*IDIM];
__device__ float g_y[(size_t)SLOT_CAP*HDIM]; // per-slot routed outputs

// ---------------- gating ----------------
__global__ void gate_kernel(const float* __restrict__ x, const float* __restrict__ gw) {
    int warp = (blockIdx.x * blockDim.x + threadIdx.x) >> 5;
    int lane = threadIdx.x & 31;
    if (warp >= N_TOK) return;
    const float* xr = x + (size_t)warp * HDIM;

    float acc[NEXP];
#pragma unroll
    for (int e = 0; e < NEXP; e++) acc[e] = 0.f;
    for (int h = lane; h < HDIM; h += 32) {
        float xv = xr[h];
#pragma unroll
        for (int e = 0; e < NEXP; e++) acc[e] += xv * gw[e*HDIM + h];
    }
#pragma unroll
    for (int e = 0; e < NEXP; e++) {
        float a = acc[e];
#pragma unroll
        for (int o = 16; o; o >>= 1) a += __shfl_xor_sync(0xffffffffu, a, o);
        acc[e] = 1.f / (1.f + expf(-a));   // sigmoid score
    }
    if (lane == 0) {
        bool used[NEXP];
#pragma unroll
        for (int e = 0; e < NEXP; e++) used[e] = false;
        int idxs[TOPK]; float vals[TOPK]; float wsum = 0.f;
        for (int k = 0; k < TOPK; k++) {
            int bi = -1; float bv = -1e30f;
            for (int e = 0; e < NEXP; e++)
                if (!used[e] && acc[e] > bv) { bv = acc[e]; bi = e; }
            used[bi] = true; idxs[k] = bi; vals[k] = bv; wsum += bv;
        }
        float inv = 1.f / (wsum + 1e-9f);
        for (int k = 0; k < TOPK; k++) {
            g_topk_idx[warp*TOPK + k] = idxs[k];
            g_topk_w[warp*TOPK + k]   = vals[k] * inv;
            atomicAdd(&g_counts[idxs[k]], 1);
        }
    }
}

__global__ void zero_counts_kernel() {
    int t = threadIdx.x;
    if (t < NEXP) { g_counts[t] = 0; g_cursor[t] = 0; }
}

__global__ void offsets_kernel() {
    if (threadIdx.x == 0) {
        int off = 0;
        for (int e = 0; e < NEXP; e++) {
            g_off[e] = off;
            int p = (g_counts[e] + BM - 1) / BM * BM;
            g_padded[e] = p;
            off += p;
        }
    }
}

__global__ void fill_slots_kernel() {
    int i = blockIdx.x * blockDim.x + threadIdx.x;
    if (i < SLOT_CAP) g_slot_token[i] = -1;
}

__global__ void scatter_kernel() {
    int i = blockIdx.x * blockDim.x + threadIdx.x;
    if (i >= N_TOK * TOPK) return;
    int e = g_topk_idx[i];
    int pos = g_off[e] + atomicAdd(&g_cursor[e], 1);
    g_slot_token[pos] = i / TOPK;
    g_slot_of[i] = pos;
}

// ---------------- SGEMM core (128x128x8, 256 threads, 8x8 microtile) ----------------
__device__ __forceinline__ void gemm_tile(
    const float* __restrict__ Abase, int a_ldk,   // A row-major, leading dim a_ldk
    const int* tok,                               // smem token list (gather) or nullptr
    const float* __restrict__ B, int Nc, int Kc,  // B row-major [Kc, Nc]
    float* __restrict__ Crow0, int col0, int accumulate)
{
    __shared__ float As[BK][BM];
    __shared__ float Bs[BK][BN];

    int tid = threadIdx.x;
    int arow = tid >> 1;
    int acol = (tid & 1) * 4;
    int brow = tid >> 5;
    int bcol = (tid & 31) * 4;
    int ty = tid >> 4;
    int tx = tid & 15;

    float acc[8][8];
#pragma unroll
    for (int i = 0; i < 8; i++)
#pragma unroll
        for (int j = 0; j < 8; j++) acc[i][j] = 0.f;

    const float* arowptr;
    bool avalid = true;
    if (tok) {
        int t = tok[arow];
        avalid = (t >= 0);
        arowptr = Abase + (size_t)(avalid ? t : 0) * a_ldk;
    } else {
        arowptr = Abase + (size_t)arow * a_ldk;
    }

    float4 av = avalid ? *(const float4*)(arowptr + acol)
                       : make_float4(0.f, 0.f, 0.f, 0.f);
    float4 bv = *(const float4*)(B + (size_t)brow * Nc + col0 + bcol);

    for (int k0 = 0; k0 < Kc; k0 += BK) {
        As[acol + 0][arow] = av.x;
        As[acol + 1][arow] = av.y;
        As[acol + 2][arow] = av.z;
        As[acol + 3][arow] = av.w;
        *(float4*)&Bs[brow][bcol] = bv;
        __syncthreads();

        int kn = k0 + BK;
        if (kn < Kc) {
            av = avalid ? *(const float4*)(arowptr + kn + acol)
                        : make_float4(0.f, 0.f, 0.f, 0.f);
            bv = *(const float4*)(B + (size_t)(kn + brow) * Nc + col0 + bcol);
        }

#pragma unroll
        for (int kk = 0; kk < BK; kk++) {
            float a0[8], b0[8];
            *(float4*)&a0[0] = *(float4*)&As[kk][ty * 8];
            *(float4*)&a0[4] = *(float4*)&As[kk][ty * 8 + 4];
            *(float4*)&b0[0] = *(float4*)&Bs[kk][tx * 8];
            *(float4*)&b0[4] = *(float4*)&Bs[kk][tx * 8 + 4];
#pragma unroll
            for (int i = 0; i < 8; i++)
#pragma unroll
                for (int j = 0; j < 8; j++) acc[i][j] += a0[i] * b0[j];
        }
        __syncthreads();
    }

#pragma unroll
    for (int i = 0; i < 8; i++) {
        float* crow = Crow0 + (size_t)(ty * 8 + i) * Nc + col0 + tx * 8;
        if (accumulate) {
            float4 c0 = *(float4*)crow;
            float4 c1 = *(float4*)(crow + 4);
            c0.x += acc[i][0]; c0.y += acc[i][1]; c0.z += acc[i][2]; c0.w += acc[i][3];
            c1.x += acc[i][4]; c1.y += acc[i][5]; c1.z += acc[i][6]; c1.w += acc[i][7];
            *(float4*)crow = c0; *(float4*)(crow + 4) = c1;
        } else {
            float4 c0 = make_float4(acc[i][0], acc[i][1], acc[i][2], acc[i][3]);
            float4 c1 = make_float4(acc[i][4], acc[i][5], acc[i][6], acc[i][7]);
            *(float4*)crow = c0; *(float4*)(crow + 4) = c1;
        }
    }
}

__global__ void __launch_bounds__(256) sgemm_plain(
    const float* __restrict__ A, const float* __restrict__ B, float* __restrict__ C,
    int Nc, int Kc, int accumulate)
{
    int row0 = blockIdx.y * BM;
    int col0 = blockIdx.x * BN;
    gemm_tile(A + (size_t)row0 * Kc, Kc, nullptr, B, Nc, Kc,
              C + (size_t)row0 * Nc, col0, accumulate);
}

// routed GEMM1: gather token rows of x, per-expert weight slice [HDIM, IDIM]
__global__ void __launch_bounds__(256) sgemm_gather(
    const float* __restrict__ X, const float* __restrict__ Wbase, float* __restrict__ Cbase)
{
    int e  = blockIdx.y >> 5;       // /TILES_PER_E
    int lt = blockIdx.y & 31;
    if (lt * BM >= g_padded[e]) return;
    int slot0 = g_off[e] + lt * BM;

    __shared__ int tok[BM];
    if (threadIdx.x < BM) tok[threadIdx.x] = g_slot_token[slot0 + threadIdx.x];
    __syncthreads();

    gemm_tile(X, HDIM, tok, Wbase + (size_t)e * HDIM * IDIM, IDIM, HDIM,
              Cbase + (size_t)slot0 * IDIM, blockIdx.x * BN, 0);
}

// routed GEMM2: [slots, IDIM] @ w2[e] [IDIM, HDIM] -> Y[slots, HDIM]
__global__ void __launch_bounds__(256) sgemm_routed2(
    const float* __restrict__ G, const float* __restrict__ W2base, float* __restrict__ Y)
{
    int e  = blockIdx.y >> 5;
    int lt = blockIdx.y & 31;
    if (lt * BM >= g_padded[e]) return;
    int slot0 = g_off[e] + lt * BM;
    gemm_tile(G + (size_t)slot0 * IDIM, IDIM, nullptr,
              W2base + (size_t)e * IDIM * HDIM, HDIM, IDIM,
              Y + (size_t)slot0 * HDIM, blockIdx.x * BN, 0);
}

// ---------------- elementwise ----------------
__global__ void silu_mul_kernel(float* __restrict__ a, const float* __restrict__ b, int n) {
    int i = blockIdx.x * blockDim.x + threadIdx.x;
    if (i < n) {
        float v = a[i];
        float s = v / (1.f + expf(-v));   // silu
        a[i] = s * b[i];
    }
}

__global__ void combine_kernel(float* __restrict__ out) {
    int n = blockIdx.x;
    int slot[TOPK]; float w[TOPK];
#pragma unroll
    for (int k = 0; k < TOPK; k++) {
        slot[k] = g_slot_of[n*TOPK + k];
        w[k]    = g_topk_w[n*TOPK + k];
    }
    for (int h = threadIdx.x * 4; h < HDIM; h += blockDim.x * 4) {
        float4 o = *(float4*)(out + (size_t)n * HDIM + h);
#pragma unroll
        for (int k = 0; k < TOPK; k++) {
            const float4 y = *(const float4*)(g_y + (size_t)slot[k] * HDIM + h);
            o.x += w[k] * y.x; o.y += w[k] * y.y;
            o.z += w[k] * y.z; o.w += w[k] * y.w;
        }
        *(float4*)(out + (size_t)n * HDIM + h) = o;
    }
}

__global__ void zero_tail_kernel(float* out, int start, int total) {
    int i = start + blockIdx.x * blockDim.x + threadIdx.x;
    if (i < total) out[i] = 0.f;
}

// ---------------- launch ----------------
extern "C" void kernel_launch(void* const* d_in, const int* in_sizes, int n_in,
                              void* d_out, int out_size) {
    const float* x   = (const float*)d_in[0];
    const float* gw  = (const float*)d_in[1];
    const float* sw1 = (const float*)d_in[2];
    const float* sw2 = (const float*)d_in[3];
    const float* sw3 = (const float*)d_in[4];
    const float* rw1 = (const float*)d_in[5];
    const float* rw2 = (const float*)d_in[6];
    const float* rw3 = (const float*)d_in[7];
    float* out = (float*)d_out;

    float *buf1, *buf3, *ybuf;
    cudaGetSymbolAddress((void**)&buf1, g_buf1);
    cudaGetSymbolAddress((void**)&buf3, g_buf3);
    cudaGetSymbolAddress((void**)&ybuf, g_y);

    // routing
    zero_counts_kernel<<<1, 32>>>();
    gate_kernel<<<N_TOK/8, 256>>>(x, gw);
    offsets_kernel<<<1, 1>>>();
    fill_slots_kernel<<<(SLOT_CAP + 255)/256, 256>>>();
    scatter_kernel<<<(N_TOK*TOPK + 255)/256, 256>>>();

    // shared experts: out = sum_e (silu(x@w1)*(x@w3)) @ w2
    for (int e = 0; e < 2; e++) {
        sgemm_plain<<<dim3(SDIM/BN, N_TOK/BM), 256>>>(x, sw1 + (size_t)e*HDIM*SDIM, buf1, SDIM, HDIM, 0);
        sgemm_plain<<<dim3(SDIM/BN, N_TOK/BM), 256>>>(x, sw3 + (size_t)e*HDIM*SDIM, buf3, SDIM, HDIM, 0);
        silu_mul_kernel<<<(N_TOK*SDIM + 255)/256, 256>>>(buf1, buf3, N_TOK*SDIM);
        sgemm_plain<<<dim3(HDIM/BN, N_TOK/BM), 256>>>(buf1, sw2 + (size_t)e*SDIM*HDIM, out, HDIM, SDIM, e);
    }

    // routed experts (sparse: only gathered slots)
    sgemm_gather<<<dim3(IDIM/BN, NEXP*TILES_PER_E), 256>>>(x, rw1, buf1);
    sgemm_gather<<<dim3(IDIM/BN, NEXP*TILES_PER_E), 256>>>(x, rw3, buf3);
    silu_mul_kernel<<<(SLOT_CAP*IDIM + 255)/256, 256>>>(buf1, buf3, SLOT_CAP*IDIM);
    sgemm_routed2<<<dim3(HDIM/BN, NEXP*TILES_PER_E), 256>>>(buf1, rw2, ybuf);

    // combine routed into out (deterministic: per-token fixed-order sum)
    combine_kernel<<<N_TOK, 256>>>(out);

    int tail = out_size - N_TOK*HDIM;
    if (tail > 0)
        zero_tail_kernel<<<(tail + 255)/256, 256>>>(out, N_TOK*HDIM, out_size);
}